// round 4
// baseline (speedup 1.0000x reference)
#include <cuda_runtime.h>
#include <cuda_bf16.h>
#include <math.h>
#include <stdint.h>

#define N_NODES 100000
#define N_EDGES 800000

typedef unsigned int u32;
typedef unsigned long long u64t;

// ---------------- scratch (static __device__ — no allocations allowed) ----------
__device__ float g_AB[(size_t)N_NODES * 256];    // [n][0:128]=x@W1a, [n][128:256]=x@W1b
__device__ float g_Hagg[(size_t)N_NODES * 128];  // sum over in-edges of relu(h)
__device__ float g_G[(size_t)N_NODES * 128];     // relu(update hidden)
__device__ float g_deg[N_NODES];                 // in-degree (float)
__device__ float g_Wcat[192 * 128];              // [U1a (64x128) ; V = W2@U1b (128x128)]
__device__ float g_dvec[128];                    // b2 @ U1b

// pre-packed mma B fragments (hi/lo bf16 pairs), layout: ((s*N + c)*4 + q)*2 + h
__device__ u32 g_Bp1hi[2 * 4096];   // GEMM1: two 64x128 matrices (W1a, W1b)
__device__ u32 g_Bp1lo[2 * 4096];
__device__ u32 g_Bp2hi[12288];      // GEMM2: 192x128 (Wcat)
__device__ u32 g_Bp2lo[12288];
__device__ u32 g_Bp3hi[4096];       // GEMM3: 128x64 (U2)
__device__ u32 g_Bp3lo[4096];

// ---------------- helpers ----------------------------------------------------------
__device__ __forceinline__ u32 bf16bits(float x) {
    return (u32)__bfloat16_as_ushort(__float2bfloat16_rn(x));
}
__device__ __forceinline__ float bf16val(float x) {
    return __bfloat162float(__float2bfloat16_rn(x));
}
__device__ __forceinline__ u32 pack_hi(float x, float y) {
    return bf16bits(x) | (bf16bits(y) << 16);
}
__device__ __forceinline__ u32 pack_lo(float x, float y) {
    return bf16bits(x - bf16val(x)) | (bf16bits(y - bf16val(y)) << 16);
}

__device__ __forceinline__ void mma16816(float c[4], const u32 a[4], u32 b0, u32 b1) {
    asm volatile(
        "mma.sync.aligned.m16n8k16.row.col.f32.bf16.bf16.f32 "
        "{%0,%1,%2,%3}, {%4,%5,%6,%7}, {%8,%9}, {%0,%1,%2,%3};"
        : "+f"(c[0]), "+f"(c[1]), "+f"(c[2]), "+f"(c[3])
        : "r"(a[0]), "r"(a[1]), "r"(a[2]), "r"(a[3]), "r"(b0), "r"(b1));
}

// ---------------- prep: build Wcat and dvec --------------------------------------
__global__ void prep_kernel(const float* __restrict__ W2, const float* __restrict__ b2,
                            const float* __restrict__ U1) {
    int b = blockIdx.x, j = threadIdx.x;  // 128 threads
    if (b < 64) {
        g_Wcat[b * 128 + j] = U1[b * 128 + j];
    } else if (b < 192) {
        int i = b - 64;
        float s = 0.f;
#pragma unroll
        for (int k = 0; k < 64; k++)
            s = fmaf(W2[i * 64 + k], U1[(64 + k) * 128 + j], s);
        g_Wcat[b * 128 + j] = s;
    } else {
        float s = 0.f;
#pragma unroll
        for (int k = 0; k < 64; k++)
            s = fmaf(b2[k], U1[(64 + k) * 128 + j], s);
        g_dvec[j] = s;
    }
}

// ---------------- pack B matrices into mma fragment layout ------------------------
__global__ void pack_b_kernel(int which, const float* __restrict__ W1,
                              const float* __restrict__ U2) {
    u32 *dh, *dl;
    const float* src;
    int K, N;
    if (which == 0)      { dh = g_Bp1hi;        dl = g_Bp1lo;        src = W1;            K = 64;  N = 128; }
    else if (which == 1) { dh = g_Bp1hi + 4096; dl = g_Bp1lo + 4096; src = W1 + 64 * 128; K = 64;  N = 128; }
    else if (which == 2) { dh = g_Bp2hi;        dl = g_Bp2lo;        src = g_Wcat;        K = 192; N = 128; }
    else                 { dh = g_Bp3hi;        dl = g_Bp3lo;        src = U2;            K = 128; N = 64;  }

    int idx = blockIdx.x * blockDim.x + threadIdx.x;
    int total = (K / 16) * N * 8;
    if (idx >= total) return;
    int h = idx & 1;
    int rest = idx >> 1;
    int q = rest & 3;
    int rest2 = rest >> 2;
    int c = rest2 % N;
    int s = rest2 / N;
    int k0 = 16 * s + 2 * q + 8 * h;
    float f0 = src[(size_t)k0 * N + c];
    float f1 = src[(size_t)(k0 + 1) * N + c];
    dh[idx] = pack_hi(f0, f1);
    dl[idx] = pack_lo(f0, f1);
}

// ---------------- zero scratch accumulators ---------------------------------------
__global__ void zero_kernel() {
    size_t idx = (size_t)blockIdx.x * blockDim.x + threadIdx.x;
    size_t stride = (size_t)gridDim.x * blockDim.x;
    size_t tot4 = (size_t)N_NODES * 128 / 4;
    float4 z = make_float4(0.f, 0.f, 0.f, 0.f);
    for (size_t i = idx; i < tot4; i += stride) ((float4*)g_Hagg)[i] = z;
    for (size_t i = idx; i < (size_t)N_NODES; i += stride) g_deg[i] = 0.f;
}

// ---------------- tensor-core GEMM (bf16 2-term split, fp32 accumulate) -----------
// MODE 0: AB[.,cb*128 + n] = x @ W1[cb]          (K=64,  NB=128)
// MODE 1: G = relu([x|Hagg]@Wcat + deg*dvec+bu1) (K=192, NB=128)
// MODE 2: out = G @ U2 + bu2                     (K=128, NB=64)
template <int KTOT, int NB, int MODE>
__global__ __launch_bounds__(256) void mma_gemm_kernel(const float* __restrict__ a_x,
                                                       const float* __restrict__ bias,
                                                       float* __restrict__ outp) {
    constexpr int NJ = NB / 16;        // per-warp n8 tiles (2 warps across N)
    constexpr int NCH = KTOT / 32;     // 32-wide K chunks
    __shared__ __align__(16) u32 sA[2][128][20];  // [hi/lo][row][k-word], pad->20

    const int tid = threadIdx.x;
    const int lane = tid & 31;
    const int warp = tid >> 5;
    const int wm = warp >> 1;          // 0..3
    const int wn = warp & 1;           // 0..1
    const int q = lane & 3;
    const int lr = lane >> 2;          // 0..7
    const int row0 = blockIdx.x * 128;
    const int cb = (MODE == 0) ? blockIdx.y : 0;

    const u32* __restrict__ Bhi;
    const u32* __restrict__ Blo;
    if (MODE == 0)      { Bhi = g_Bp1hi + cb * 4096; Blo = g_Bp1lo + cb * 4096; }
    else if (MODE == 1) { Bhi = g_Bp2hi;             Blo = g_Bp2lo; }
    else                { Bhi = g_Bp3hi;             Blo = g_Bp3lo; }

    float acc[2][NJ][4];
#pragma unroll
    for (int i = 0; i < 2; i++)
#pragma unroll
        for (int j = 0; j < NJ; j++)
#pragma unroll
            for (int p = 0; p < 4; p++) acc[i][j][p] = 0.f;

    for (int ch = 0; ch < NCH; ch++) {
        const int kc0 = ch * 32;
        const float* srcp;
        int ld, koff;
        if (MODE == 0)      { srcp = a_x; ld = 64; koff = kc0; }
        else if (MODE == 1) {
            if (kc0 < 64) { srcp = a_x;              ld = 64;  koff = kc0; }
            else          { srcp = (const float*)g_Hagg; ld = 128; koff = kc0 - 64; }
        } else              { srcp = (const float*)g_G; ld = 128; koff = kc0; }

        __syncthreads();
#pragma unroll
        for (int it = 0; it < 4; it++) {
            int idx = tid + it * 256;
            int m = idx >> 3, fx = idx & 7;
            int gm = row0 + m;
            if (gm >= N_NODES) gm = N_NODES - 1;  // clamp; masked at store
            float4 v = *(const float4*)(srcp + (size_t)gm * ld + koff + fx * 4);
            u32 h0 = pack_hi(v.x, v.y), h1 = pack_hi(v.z, v.w);
            u32 l0 = pack_lo(v.x, v.y), l1 = pack_lo(v.z, v.w);
            *(u64t*)&sA[0][m][fx * 2] = ((u64t)h1 << 32) | h0;
            *(u64t*)&sA[1][m][fx * 2] = ((u64t)l1 << 32) | l0;
        }
        __syncthreads();

#pragma unroll
        for (int s = 0; s < 2; s++) {
            const int sg = ch * 2 + s;
            u32 ah[2][4], al[2][4];
#pragma unroll
            for (int i = 0; i < 2; i++) {
                int rr = wm * 32 + i * 16 + lr;
                ah[i][0] = sA[0][rr][8 * s + q];
                ah[i][1] = sA[0][rr + 8][8 * s + q];
                ah[i][2] = sA[0][rr][8 * s + q + 4];
                ah[i][3] = sA[0][rr + 8][8 * s + q + 4];
                al[i][0] = sA[1][rr][8 * s + q];
                al[i][1] = sA[1][rr + 8][8 * s + q];
                al[i][2] = sA[1][rr][8 * s + q + 4];
                al[i][3] = sA[1][rr + 8][8 * s + q + 4];
            }
#pragma unroll
            for (int j = 0; j < NJ; j++) {
                int c = wn * (NB / 2) + j * 8 + lr;
                int bidx = ((sg * NB + c) * 4 + q) * 2;
                u64t bh = *(const u64t*)(Bhi + bidx);
                u64t bl = *(const u64t*)(Blo + bidx);
                u32 bh0 = (u32)bh, bh1 = (u32)(bh >> 32);
                u32 bl0 = (u32)bl, bl1 = (u32)(bl >> 32);
#pragma unroll
                for (int i = 0; i < 2; i++) {
                    mma16816(acc[i][j], ah[i], bh0, bh1);
                    mma16816(acc[i][j], al[i], bh0, bh1);
                    mma16816(acc[i][j], ah[i], bl0, bl1);
                }
            }
        }
    }

    // ---------------- epilogue ----------------
    const int rbase = row0 + wm * 32 + lr;
#pragma unroll
    for (int i = 0; i < 2; i++) {
        int r0 = rbase + i * 16;
        int r1 = r0 + 8;
#pragma unroll
        for (int j = 0; j < NJ; j++) {
            int n = wn * (NB / 2) + j * 8 + 2 * q;
            float c0 = acc[i][j][0], c1 = acc[i][j][1];
            float c2 = acc[i][j][2], c3 = acc[i][j][3];
            if (MODE == 0) {
                if (r0 < N_NODES)
                    *(float2*)(g_AB + (size_t)r0 * 256 + cb * 128 + n) = make_float2(c0, c1);
                if (r1 < N_NODES)
                    *(float2*)(g_AB + (size_t)r1 * 256 + cb * 128 + n) = make_float2(c2, c3);
            } else if (MODE == 1) {
                float dv0 = g_dvec[n], dv1 = g_dvec[n + 1];
                float bu0 = bias[n], bu1v = bias[n + 1];
                if (r0 < N_NODES) {
                    float dg = g_deg[r0];
                    *(float2*)(g_G + (size_t)r0 * 128 + n) =
                        make_float2(fmaxf(c0 + fmaf(dg, dv0, bu0), 0.f),
                                    fmaxf(c1 + fmaf(dg, dv1, bu1v), 0.f));
                }
                if (r1 < N_NODES) {
                    float dg = g_deg[r1];
                    *(float2*)(g_G + (size_t)r1 * 128 + n) =
                        make_float2(fmaxf(c2 + fmaf(dg, dv0, bu0), 0.f),
                                    fmaxf(c3 + fmaf(dg, dv1, bu1v), 0.f));
                }
            } else {
                float bu0 = bias[n], bu1v = bias[n + 1];
                if (r0 < N_NODES)
                    *(float2*)(outp + (size_t)r0 * 64 + n) = make_float2(c0 + bu0, c1 + bu1v);
                if (r1 < N_NODES)
                    *(float2*)(outp + (size_t)r1 * 64 + n) = make_float2(c2 + bu0, c3 + bu1v);
            }
        }
    }
}

// ---------------- edge kernel (R1 version: 1 edge/warp) ---------------------------
__global__ __launch_bounds__(256) void edge_kernel(const int* __restrict__ ei,
                                                   const float* __restrict__ ef,
                                                   const float* __restrict__ W1,
                                                   const float* __restrict__ b1) {
    __shared__ float s_wc[512];
    __shared__ float s_b1[128];
    for (int t = threadIdx.x; t < 512; t += 256) s_wc[t] = W1[128 * 128 + t];
    if (threadIdx.x < 128) s_b1[threadIdx.x] = b1[threadIdx.x];
    __syncthreads();

    int warp = threadIdx.x >> 5;
    int lane = threadIdx.x & 31;
    int e = blockIdx.x * 8 + warp;
    if (e >= N_EDGES) return;
    int src = ei[e];
    int dst = ei[N_EDGES + e];

    float mv = 0.f;
    if (lane < 4) mv = log1pf(ef[(size_t)e * 4 + lane]);
    float l0 = __shfl_sync(0xffffffffu, mv, 0);
    float l1 = __shfl_sync(0xffffffffu, mv, 1);
    float l2 = __shfl_sync(0xffffffffu, mv, 2);
    float l3 = __shfl_sync(0xffffffffu, mv, 3);

    float4 a = *(const float4*)(g_AB + (size_t)src * 256 + lane * 4);
    float4 b = *(const float4*)(g_AB + (size_t)dst * 256 + 128 + lane * 4);
    float4 w0 = *(const float4*)&s_wc[0 * 128 + lane * 4];
    float4 w1 = *(const float4*)&s_wc[1 * 128 + lane * 4];
    float4 w2 = *(const float4*)&s_wc[2 * 128 + lane * 4];
    float4 w3 = *(const float4*)&s_wc[3 * 128 + lane * 4];
    float4 bb = *(const float4*)&s_b1[lane * 4];

    float4 h;
    h.x = fmaxf(fmaf(l3, w3.x, fmaf(l2, w2.x, fmaf(l1, w1.x, fmaf(l0, w0.x, a.x + b.x + bb.x)))), 0.f);
    h.y = fmaxf(fmaf(l3, w3.y, fmaf(l2, w2.y, fmaf(l1, w1.y, fmaf(l0, w0.y, a.y + b.y + bb.y)))), 0.f);
    h.z = fmaxf(fmaf(l3, w3.z, fmaf(l2, w2.z, fmaf(l1, w1.z, fmaf(l0, w0.z, a.z + b.z + bb.z)))), 0.f);
    h.w = fmaxf(fmaf(l3, w3.w, fmaf(l2, w2.w, fmaf(l1, w1.w, fmaf(l0, w0.w, a.w + b.w + bb.w)))), 0.f);

    atomicAdd((float4*)(g_Hagg + (size_t)dst * 128 + lane * 4), h);
    if (lane == 0) atomicAdd(&g_deg[dst], 1.0f);
}

// ---------------- launch ----------------------------------------------------------
extern "C" void kernel_launch(void* const* d_in, const int* in_sizes, int n_in,
                              void* d_out, int out_size) {
    const float* x   = (const float*)d_in[0];
    const int*   ei  = (const int*)d_in[1];
    const float* ef  = (const float*)d_in[2];
    const float* W1  = (const float*)d_in[3];
    const float* b1  = (const float*)d_in[4];
    const float* W2  = (const float*)d_in[5];
    const float* b2  = (const float*)d_in[6];
    const float* U1  = (const float*)d_in[7];
    const float* bu1 = (const float*)d_in[8];
    const float* U2  = (const float*)d_in[9];
    const float* bu2 = (const float*)d_in[10];
    float* out = (float*)d_out;

    prep_kernel<<<193, 128>>>(W2, b2, U1);
    pack_b_kernel<<<16, 256>>>(0, W1, U2);
    pack_b_kernel<<<16, 256>>>(1, W1, U2);
    pack_b_kernel<<<48, 256>>>(2, W1, U2);
    pack_b_kernel<<<16, 256>>>(3, W1, U2);
    zero_kernel<<<1184, 256>>>();
    mma_gemm_kernel<64, 128, 0><<<dim3(782, 2), 256>>>(x, nullptr, nullptr);
    edge_kernel<<<(N_EDGES + 7) / 8, 256>>>(ei, ef, W1, b1);
    mma_gemm_kernel<192, 128, 1><<<782, 256>>>(x, bu1, nullptr);
    mma_gemm_kernel<128, 64, 2><<<782, 256>>>(x, bu2, out);
}

// round 5
// speedup vs baseline: 1.0096x; 1.0096x over previous
#include <cuda_runtime.h>
#include <cuda_bf16.h>
#include <math.h>
#include <stdint.h>

#define N_NODES 100000
#define N_EDGES 800000

typedef unsigned int u32;
typedef unsigned long long u64t;

// ---------------- scratch (static __device__ — no allocations allowed) ----------
__device__ float g_AB[(size_t)N_NODES * 256];    // [n][0:128]=x@W1a, [n][128:256]=x@W1b
__device__ float g_Hagg[(size_t)N_NODES * 128];  // sum over in-edges of relu(h)
__device__ float g_G[(size_t)N_NODES * 128];     // relu(update hidden)
__device__ float g_deg[N_NODES];                 // in-degree (float)
__device__ float g_Wcat[192 * 128];              // [U1a (64x128) ; V = W2@U1b (128x128)]
__device__ float g_dvec[128];                    // b2 @ U1b

// pre-packed mma B fragments (hi/lo bf16 pairs), layout: ((s*N + c)*4 + q)*2 + h
__device__ u32 g_Bp1hi[2 * 4096];   // GEMM1: two 64x128 matrices (W1a, W1b)
__device__ u32 g_Bp1lo[2 * 4096];
__device__ u32 g_Bp2hi[12288];      // GEMM2: 192x128 (Wcat)
__device__ u32 g_Bp2lo[12288];
__device__ u32 g_Bp3hi[4096];       // GEMM3: 128x64 (U2)
__device__ u32 g_Bp3lo[4096];

// ---------------- helpers ----------------------------------------------------------
__device__ __forceinline__ u32 bf16bits(float x) {
    return (u32)__bfloat16_as_ushort(__float2bfloat16_rn(x));
}
__device__ __forceinline__ float bf16val(float x) {
    return __bfloat162float(__float2bfloat16_rn(x));
}
__device__ __forceinline__ u32 pack_hi(float x, float y) {
    return bf16bits(x) | (bf16bits(y) << 16);
}
__device__ __forceinline__ u32 pack_lo(float x, float y) {
    return bf16bits(x - bf16val(x)) | (bf16bits(y - bf16val(y)) << 16);
}

__device__ __forceinline__ void mma16816(float c[4], const u32 a[4], u32 b0, u32 b1) {
    asm volatile(
        "mma.sync.aligned.m16n8k16.row.col.f32.bf16.bf16.f32 "
        "{%0,%1,%2,%3}, {%4,%5,%6,%7}, {%8,%9}, {%0,%1,%2,%3};"
        : "+f"(c[0]), "+f"(c[1]), "+f"(c[2]), "+f"(c[3])
        : "r"(a[0]), "r"(a[1]), "r"(a[2]), "r"(a[3]), "r"(b0), "r"(b1));
}

// ---------------- prep: build Wcat and dvec --------------------------------------
__global__ void prep_kernel(const float* __restrict__ W2, const float* __restrict__ b2,
                            const float* __restrict__ U1) {
    int b = blockIdx.x, j = threadIdx.x;  // 128 threads
    if (b < 64) {
        g_Wcat[b * 128 + j] = U1[b * 128 + j];
    } else if (b < 192) {
        int i = b - 64;
        float s = 0.f;
#pragma unroll
        for (int k = 0; k < 64; k++)
            s = fmaf(W2[i * 64 + k], U1[(64 + k) * 128 + j], s);
        g_Wcat[b * 128 + j] = s;
    } else {
        float s = 0.f;
#pragma unroll
        for (int k = 0; k < 64; k++)
            s = fmaf(b2[k], U1[(64 + k) * 128 + j], s);
        g_dvec[j] = s;
    }
}

// ---------------- pack B matrices into mma fragment layout ------------------------
__global__ void pack_b_kernel(int which, const float* __restrict__ W1,
                              const float* __restrict__ U2) {
    u32 *dh, *dl;
    const float* src;
    int K, N;
    if (which == 0)      { dh = g_Bp1hi;        dl = g_Bp1lo;        src = W1;            K = 64;  N = 128; }
    else if (which == 1) { dh = g_Bp1hi + 4096; dl = g_Bp1lo + 4096; src = W1 + 64 * 128; K = 64;  N = 128; }
    else if (which == 2) { dh = g_Bp2hi;        dl = g_Bp2lo;        src = g_Wcat;        K = 192; N = 128; }
    else                 { dh = g_Bp3hi;        dl = g_Bp3lo;        src = U2;            K = 128; N = 64;  }

    int idx = blockIdx.x * blockDim.x + threadIdx.x;
    int total = (K / 16) * N * 8;
    if (idx >= total) return;
    int h = idx & 1;
    int rest = idx >> 1;
    int q = rest & 3;
    int rest2 = rest >> 2;
    int c = rest2 % N;
    int s = rest2 / N;
    int k0 = 16 * s + 2 * q + 8 * h;
    float f0 = src[(size_t)k0 * N + c];
    float f1 = src[(size_t)(k0 + 1) * N + c];
    dh[idx] = pack_hi(f0, f1);
    dl[idx] = pack_lo(f0, f1);
}

// ---------------- zero scratch accumulators ---------------------------------------
__global__ void zero_kernel() {
    size_t idx = (size_t)blockIdx.x * blockDim.x + threadIdx.x;
    size_t stride = (size_t)gridDim.x * blockDim.x;
    size_t tot4 = (size_t)N_NODES * 128 / 4;
    float4 z = make_float4(0.f, 0.f, 0.f, 0.f);
    for (size_t i = idx; i < tot4; i += stride) ((float4*)g_Hagg)[i] = z;
    for (size_t i = idx; i < (size_t)N_NODES; i += stride) g_deg[i] = 0.f;
}

// ---------------- tensor-core GEMM (bf16 2-term split, fp32 accumulate) -----------
// MODE 0: AB[.,cb*128 + n] = x @ W1[cb]          (K=64,  NB=128)
// MODE 1: G = relu([x|Hagg]@Wcat + deg*dvec+bu1) (K=192, NB=128)
// MODE 2: out = G @ U2 + bu2                     (K=128, NB=64)
template <int KTOT, int NB, int MODE>
__global__ __launch_bounds__(256) void mma_gemm_kernel(const float* __restrict__ a_x,
                                                       const float* __restrict__ bias,
                                                       float* __restrict__ outp) {
    constexpr int NJ = NB / 16;        // per-warp n8 tiles (2 warps across N)
    constexpr int NCH = KTOT / 32;     // 32-wide K chunks
    __shared__ __align__(16) u32 sA[2][128][20];  // [hi/lo][row][k-word], pad->20

    const int tid = threadIdx.x;
    const int lane = tid & 31;
    const int warp = tid >> 5;
    const int wm = warp >> 1;          // 0..3
    const int wn = warp & 1;           // 0..1
    const int q = lane & 3;
    const int lr = lane >> 2;          // 0..7
    const int row0 = blockIdx.x * 128;
    const int cb = (MODE == 0) ? blockIdx.y : 0;

    const u32* __restrict__ Bhi;
    const u32* __restrict__ Blo;
    if (MODE == 0)      { Bhi = g_Bp1hi + cb * 4096; Blo = g_Bp1lo + cb * 4096; }
    else if (MODE == 1) { Bhi = g_Bp2hi;             Blo = g_Bp2lo; }
    else                { Bhi = g_Bp3hi;             Blo = g_Bp3lo; }

    float acc[2][NJ][4];
#pragma unroll
    for (int i = 0; i < 2; i++)
#pragma unroll
        for (int j = 0; j < NJ; j++)
#pragma unroll
            for (int p = 0; p < 4; p++) acc[i][j][p] = 0.f;

    for (int ch = 0; ch < NCH; ch++) {
        const int kc0 = ch * 32;
        const float* srcp;
        int ld, koff;
        if (MODE == 0)      { srcp = a_x; ld = 64; koff = kc0; }
        else if (MODE == 1) {
            if (kc0 < 64) { srcp = a_x;              ld = 64;  koff = kc0; }
            else          { srcp = (const float*)g_Hagg; ld = 128; koff = kc0 - 64; }
        } else              { srcp = (const float*)g_G; ld = 128; koff = kc0; }

        __syncthreads();
#pragma unroll
        for (int it = 0; it < 4; it++) {
            int idx = tid + it * 256;
            int m = idx >> 3, fx = idx & 7;
            int gm = row0 + m;
            if (gm >= N_NODES) gm = N_NODES - 1;  // clamp; masked at store
            float4 v = *(const float4*)(srcp + (size_t)gm * ld + koff + fx * 4);
            u32 h0 = pack_hi(v.x, v.y), h1 = pack_hi(v.z, v.w);
            u32 l0 = pack_lo(v.x, v.y), l1 = pack_lo(v.z, v.w);
            *(u64t*)&sA[0][m][fx * 2] = ((u64t)h1 << 32) | h0;
            *(u64t*)&sA[1][m][fx * 2] = ((u64t)l1 << 32) | l0;
        }
        __syncthreads();

#pragma unroll
        for (int s = 0; s < 2; s++) {
            const int sg = ch * 2 + s;
            u32 ah[2][4], al[2][4];
#pragma unroll
            for (int i = 0; i < 2; i++) {
                int rr = wm * 32 + i * 16 + lr;
                ah[i][0] = sA[0][rr][8 * s + q];
                ah[i][1] = sA[0][rr + 8][8 * s + q];
                ah[i][2] = sA[0][rr][8 * s + q + 4];
                ah[i][3] = sA[0][rr + 8][8 * s + q + 4];
                al[i][0] = sA[1][rr][8 * s + q];
                al[i][1] = sA[1][rr + 8][8 * s + q];
                al[i][2] = sA[1][rr][8 * s + q + 4];
                al[i][3] = sA[1][rr + 8][8 * s + q + 4];
            }
#pragma unroll
            for (int j = 0; j < NJ; j++) {
                int c = wn * (NB / 2) + j * 8 + lr;
                int bidx = ((sg * NB + c) * 4 + q) * 2;
                u64t bh = *(const u64t*)(Bhi + bidx);
                u64t bl = *(const u64t*)(Blo + bidx);
                u32 bh0 = (u32)bh, bh1 = (u32)(bh >> 32);
                u32 bl0 = (u32)bl, bl1 = (u32)(bl >> 32);
#pragma unroll
                for (int i = 0; i < 2; i++) {
                    mma16816(acc[i][j], ah[i], bh0, bh1);
                    mma16816(acc[i][j], al[i], bh0, bh1);
                    mma16816(acc[i][j], ah[i], bl0, bl1);
                }
            }
        }
    }

    // ---------------- epilogue ----------------
    const int rbase = row0 + wm * 32 + lr;
#pragma unroll
    for (int i = 0; i < 2; i++) {
        int r0 = rbase + i * 16;
        int r1 = r0 + 8;
#pragma unroll
        for (int j = 0; j < NJ; j++) {
            int n = wn * (NB / 2) + j * 8 + 2 * q;
            float c0 = acc[i][j][0], c1 = acc[i][j][1];
            float c2 = acc[i][j][2], c3 = acc[i][j][3];
            if (MODE == 0) {
                if (r0 < N_NODES)
                    *(float2*)(g_AB + (size_t)r0 * 256 + cb * 128 + n) = make_float2(c0, c1);
                if (r1 < N_NODES)
                    *(float2*)(g_AB + (size_t)r1 * 256 + cb * 128 + n) = make_float2(c2, c3);
            } else if (MODE == 1) {
                float dv0 = g_dvec[n], dv1 = g_dvec[n + 1];
                float bu0 = bias[n], bu1v = bias[n + 1];
                if (r0 < N_NODES) {
                    float dg = g_deg[r0];
                    *(float2*)(g_G + (size_t)r0 * 128 + n) =
                        make_float2(fmaxf(c0 + fmaf(dg, dv0, bu0), 0.f),
                                    fmaxf(c1 + fmaf(dg, dv1, bu1v), 0.f));
                }
                if (r1 < N_NODES) {
                    float dg = g_deg[r1];
                    *(float2*)(g_G + (size_t)r1 * 128 + n) =
                        make_float2(fmaxf(c2 + fmaf(dg, dv0, bu0), 0.f),
                                    fmaxf(c3 + fmaf(dg, dv1, bu1v), 0.f));
                }
            } else {
                float bu0 = bias[n], bu1v = bias[n + 1];
                if (r0 < N_NODES)
                    *(float2*)(outp + (size_t)r0 * 64 + n) = make_float2(c0 + bu0, c1 + bu1v);
                if (r1 < N_NODES)
                    *(float2*)(outp + (size_t)r1 * 64 + n) = make_float2(c2 + bu0, c3 + bu1v);
            }
        }
    }
}

// ---------------- edge kernel (R1 version: 1 edge/warp) ---------------------------
__global__ __launch_bounds__(256) void edge_kernel(const int* __restrict__ ei,
                                                   const float* __restrict__ ef,
                                                   const float* __restrict__ W1,
                                                   const float* __restrict__ b1) {
    __shared__ float s_wc[512];
    __shared__ float s_b1[128];
    for (int t = threadIdx.x; t < 512; t += 256) s_wc[t] = W1[128 * 128 + t];
    if (threadIdx.x < 128) s_b1[threadIdx.x] = b1[threadIdx.x];
    __syncthreads();

    int warp = threadIdx.x >> 5;
    int lane = threadIdx.x & 31;
    int e = blockIdx.x * 8 + warp;
    if (e >= N_EDGES) return;
    int src = ei[e];
    int dst = ei[N_EDGES + e];

    float mv = 0.f;
    if (lane < 4) mv = log1pf(ef[(size_t)e * 4 + lane]);
    float l0 = __shfl_sync(0xffffffffu, mv, 0);
    float l1 = __shfl_sync(0xffffffffu, mv, 1);
    float l2 = __shfl_sync(0xffffffffu, mv, 2);
    float l3 = __shfl_sync(0xffffffffu, mv, 3);

    float4 a = *(const float4*)(g_AB + (size_t)src * 256 + lane * 4);
    float4 b = *(const float4*)(g_AB + (size_t)dst * 256 + 128 + lane * 4);
    float4 w0 = *(const float4*)&s_wc[0 * 128 + lane * 4];
    float4 w1 = *(const float4*)&s_wc[1 * 128 + lane * 4];
    float4 w2 = *(const float4*)&s_wc[2 * 128 + lane * 4];
    float4 w3 = *(const float4*)&s_wc[3 * 128 + lane * 4];
    float4 bb = *(const float4*)&s_b1[lane * 4];

    float4 h;
    h.x = fmaxf(fmaf(l3, w3.x, fmaf(l2, w2.x, fmaf(l1, w1.x, fmaf(l0, w0.x, a.x + b.x + bb.x)))), 0.f);
    h.y = fmaxf(fmaf(l3, w3.y, fmaf(l2, w2.y, fmaf(l1, w1.y, fmaf(l0, w0.y, a.y + b.y + bb.y)))), 0.f);
    h.z = fmaxf(fmaf(l3, w3.z, fmaf(l2, w2.z, fmaf(l1, w1.z, fmaf(l0, w0.z, a.z + b.z + bb.z)))), 0.f);
    h.w = fmaxf(fmaf(l3, w3.w, fmaf(l2, w2.w, fmaf(l1, w1.w, fmaf(l0, w0.w, a.w + b.w + bb.w)))), 0.f);

    atomicAdd((float4*)(g_Hagg + (size_t)dst * 128 + lane * 4), h);
    if (lane == 0) atomicAdd(&g_deg[dst], 1.0f);
}

// ---------------- launch ----------------------------------------------------------
extern "C" void kernel_launch(void* const* d_in, const int* in_sizes, int n_in,
                              void* d_out, int out_size) {
    const float* x   = (const float*)d_in[0];
    const int*   ei  = (const int*)d_in[1];
    const float* ef  = (const float*)d_in[2];
    const float* W1  = (const float*)d_in[3];
    const float* b1  = (const float*)d_in[4];
    const float* W2  = (const float*)d_in[5];
    const float* b2  = (const float*)d_in[6];
    const float* U1  = (const float*)d_in[7];
    const float* bu1 = (const float*)d_in[8];
    const float* U2  = (const float*)d_in[9];
    const float* bu2 = (const float*)d_in[10];
    float* out = (float*)d_out;

    prep_kernel<<<193, 128>>>(W2, b2, U1);
    pack_b_kernel<<<16, 256>>>(0, W1, U2);
    pack_b_kernel<<<16, 256>>>(1, W1, U2);
    pack_b_kernel<<<48, 256>>>(2, W1, U2);
    pack_b_kernel<<<16, 256>>>(3, W1, U2);
    zero_kernel<<<1184, 256>>>();
    mma_gemm_kernel<64, 128, 0><<<dim3(782, 2), 256>>>(x, nullptr, nullptr);
    edge_kernel<<<(N_EDGES + 7) / 8, 256>>>(ei, ef, W1, b1);
    mma_gemm_kernel<192, 128, 1><<<782, 256>>>(x, bu1, nullptr);
    mma_gemm_kernel<128, 64, 2><<<782, 256>>>(x, bu2, out);
}

// round 6
// speedup vs baseline: 1.3200x; 1.3074x over previous
#include <cuda_runtime.h>
#include <cuda_bf16.h>
#include <math.h>
#include <stdint.h>

#define N_NODES 100000
#define N_EDGES 800000
#define SCAN_BLOCKS 391   // ceil(100000/256)

typedef unsigned int u32;
typedef unsigned long long u64t;

// ---------------- scratch ----------------------------------------------------------
__device__ float g_AB[(size_t)N_NODES * 256];    // [n][0:128]=x@W1a, [n][128:256]=x@W1b
__device__ float g_Hagg[(size_t)N_NODES * 128];  // sum over in-edges of relu(h)
__device__ float g_Wcat[192 * 128];              // [U1a ; V=W2@U1b]
__device__ float g_dvec[128];                    // b2 @ U1b

// CSR by destination
__device__ int    g_cnt[N_NODES];
__device__ int    g_rp[N_NODES + 1];
__device__ int    g_pos[N_NODES];
__device__ int    g_blksum[SCAN_BLOCKS];
__device__ int    g_blkoff[SCAN_BLOCKS];
__device__ int    g_esrc[N_EDGES];
__device__ float4 g_el[N_EDGES];                 // log1p(edge features), CSR order

// pre-packed mma B fragments (hi/lo bf16 pairs), layout: ((s*N + c)*4 + q)*2 + h
__device__ u32 g_Bp1hi[2 * 4096];
__device__ u32 g_Bp1lo[2 * 4096];
__device__ u32 g_Bp2hi[12288];
__device__ u32 g_Bp2lo[12288];
__device__ u32 g_Bp3hi[4096];
__device__ u32 g_Bp3lo[4096];

// ---------------- helpers ----------------------------------------------------------
__device__ __forceinline__ u32 bf16bits(float x) {
    return (u32)__bfloat16_as_ushort(__float2bfloat16_rn(x));
}
__device__ __forceinline__ float bf16val(float x) {
    return __bfloat162float(__float2bfloat16_rn(x));
}
__device__ __forceinline__ u32 pack_hi(float x, float y) {
    return bf16bits(x) | (bf16bits(y) << 16);
}
__device__ __forceinline__ u32 pack_lo(float x, float y) {
    return bf16bits(x - bf16val(x)) | (bf16bits(y - bf16val(y)) << 16);
}

__device__ __forceinline__ void mma16816(float c[4], const u32 a[4], u32 b0, u32 b1) {
    asm volatile(
        "mma.sync.aligned.m16n8k16.row.col.f32.bf16.bf16.f32 "
        "{%0,%1,%2,%3}, {%4,%5,%6,%7}, {%8,%9}, {%0,%1,%2,%3};"
        : "+f"(c[0]), "+f"(c[1]), "+f"(c[2]), "+f"(c[3])
        : "r"(a[0]), "r"(a[1]), "r"(a[2]), "r"(a[3]), "r"(b0), "r"(b1));
}

// ---------------- prep: build Wcat and dvec ---------------------------------------
__global__ void prep_kernel(const float* __restrict__ W2, const float* __restrict__ b2,
                            const float* __restrict__ U1) {
    int b = blockIdx.x, j = threadIdx.x;
    if (b < 64) {
        g_Wcat[b * 128 + j] = U1[b * 128 + j];
    } else if (b < 192) {
        int i = b - 64;
        float s = 0.f;
#pragma unroll
        for (int k = 0; k < 64; k++)
            s = fmaf(W2[i * 64 + k], U1[(64 + k) * 128 + j], s);
        g_Wcat[b * 128 + j] = s;
    } else {
        float s = 0.f;
#pragma unroll
        for (int k = 0; k < 64; k++)
            s = fmaf(b2[k], U1[(64 + k) * 128 + j], s);
        g_dvec[j] = s;
    }
}

// ---------------- pack all B matrices (one launch) --------------------------------
__global__ void pack_all_kernel(const float* __restrict__ W1, const float* __restrict__ U2) {
    int idx = blockIdx.x * blockDim.x + threadIdx.x;  // 0 .. 24575
    u32 *dh, *dl;
    const float* src;
    int N;
    if (idx < 4096)        { dh = g_Bp1hi;        dl = g_Bp1lo;        src = W1;            N = 128; }
    else if (idx < 8192)   { dh = g_Bp1hi + 4096; dl = g_Bp1lo + 4096; src = W1 + 64 * 128; N = 128; idx -= 4096; }
    else if (idx < 20480)  { dh = g_Bp2hi;        dl = g_Bp2lo;        src = g_Wcat;        N = 128; idx -= 8192; }
    else                   { dh = g_Bp3hi;        dl = g_Bp3lo;        src = U2;            N = 64;  idx -= 20480; }

    int h = idx & 1;
    int rest = idx >> 1;
    int q = rest & 3;
    int rest2 = rest >> 2;
    int c = rest2 % N;
    int s = rest2 / N;
    int k0 = 16 * s + 2 * q + 8 * h;
    float f0 = src[(size_t)k0 * N + c];
    float f1 = src[(size_t)(k0 + 1) * N + c];
    dh[idx] = pack_hi(f0, f1);
    dl[idx] = pack_lo(f0, f1);
}

// ---------------- CSR build --------------------------------------------------------
__global__ void zero_cnt_kernel() {
    int i = blockIdx.x * blockDim.x + threadIdx.x;
    if (i < N_NODES) g_cnt[i] = 0;
}

__global__ void hist_kernel(const int* __restrict__ ei) {
    int e = blockIdx.x * blockDim.x + threadIdx.x;
    if (e < N_EDGES) atomicAdd(&g_cnt[ei[N_EDGES + e]], 1);
}

__global__ void scan_blk_kernel() {
    __shared__ int sh[256];
    int t = threadIdx.x;
    int i = blockIdx.x * 256 + t;
    int c = (i < N_NODES) ? g_cnt[i] : 0;
    sh[t] = c;
    __syncthreads();
    for (int off = 128; off > 0; off >>= 1) {
        if (t < off) sh[t] += sh[t + off];
        __syncthreads();
    }
    if (t == 0) g_blksum[blockIdx.x] = sh[0];
}

__global__ void scan_top_kernel() {
    __shared__ int sh[512];
    int t = threadIdx.x;
    int v = (t < SCAN_BLOCKS) ? g_blksum[t] : 0;
    sh[t] = v;
    __syncthreads();
    for (int off = 1; off < 512; off <<= 1) {
        int add = (t >= off) ? sh[t - off] : 0;
        __syncthreads();
        sh[t] += add;
        __syncthreads();
    }
    if (t < SCAN_BLOCKS) g_blkoff[t] = sh[t] - v;  // exclusive
    if (t == 0) g_rp[N_NODES] = N_EDGES;
}

__global__ void scan_fin_kernel() {
    __shared__ int sh[256];
    int t = threadIdx.x;
    int i = blockIdx.x * 256 + t;
    int c = (i < N_NODES) ? g_cnt[i] : 0;
    sh[t] = c;
    __syncthreads();
    for (int off = 1; off < 256; off <<= 1) {
        int add = (t >= off) ? sh[t - off] : 0;
        __syncthreads();
        sh[t] += add;
        __syncthreads();
    }
    if (i < N_NODES) {
        int excl = g_blkoff[blockIdx.x] + sh[t] - c;
        g_rp[i] = excl;
        g_pos[i] = excl;
    }
}

__global__ void scatter_kernel(const int* __restrict__ ei, const float* __restrict__ ef) {
    int e = blockIdx.x * blockDim.x + threadIdx.x;
    if (e >= N_EDGES) return;
    int s = ei[e];
    int d = ei[N_EDGES + e];
    int p = atomicAdd(&g_pos[d], 1);
    g_esrc[p] = s;
    float4 l;
    l.x = log1pf(ef[(size_t)e * 4 + 0]);
    l.y = log1pf(ef[(size_t)e * 4 + 1]);
    l.z = log1pf(ef[(size_t)e * 4 + 2]);
    l.w = log1pf(ef[(size_t)e * 4 + 3]);
    g_el[e < N_EDGES ? p : 0] = l;
}

// ---------------- aggregation: warp per destination node --------------------------
__global__ __launch_bounds__(256) void agg_kernel(const float* __restrict__ W1,
                                                  const float* __restrict__ b1) {
    __shared__ float s_wc[512];
    __shared__ float s_b1[128];
    for (int t = threadIdx.x; t < 512; t += 256) s_wc[t] = W1[128 * 128 + t];
    if (threadIdx.x < 128) s_b1[threadIdx.x] = b1[threadIdx.x];
    __syncthreads();

    int warp = threadIdx.x >> 5;
    int lane = threadIdx.x & 31;
    int d = blockIdx.x * 8 + warp;   // grid = 12500 -> exactly 100000
    int s = g_rp[d];
    int e = g_rp[d + 1];

    float4 w0 = *(const float4*)&s_wc[0 * 128 + lane * 4];
    float4 w1 = *(const float4*)&s_wc[1 * 128 + lane * 4];
    float4 w2 = *(const float4*)&s_wc[2 * 128 + lane * 4];
    float4 w3 = *(const float4*)&s_wc[3 * 128 + lane * 4];
    float4 base = *(const float4*)(g_AB + (size_t)d * 256 + 128 + lane * 4);
    float4 bb = *(const float4*)&s_b1[lane * 4];
    base.x += bb.x; base.y += bb.y; base.z += bb.z; base.w += bb.w;

    float4 acc = make_float4(0.f, 0.f, 0.f, 0.f);
    int i = s;
    for (; i + 2 <= e; i += 2) {
        int s0 = g_esrc[i], s1 = g_esrc[i + 1];
        float4 l0 = g_el[i];
        float4 l1 = g_el[i + 1];
        float4 a0 = *(const float4*)(g_AB + (size_t)s0 * 256 + lane * 4);
        float4 a1 = *(const float4*)(g_AB + (size_t)s1 * 256 + lane * 4);
        float4 h;
        h.x = fmaxf(fmaf(l0.w, w3.x, fmaf(l0.z, w2.x, fmaf(l0.y, w1.x, fmaf(l0.x, w0.x, a0.x + base.x)))), 0.f);
        h.y = fmaxf(fmaf(l0.w, w3.y, fmaf(l0.z, w2.y, fmaf(l0.y, w1.y, fmaf(l0.x, w0.y, a0.y + base.y)))), 0.f);
        h.z = fmaxf(fmaf(l0.w, w3.z, fmaf(l0.z, w2.z, fmaf(l0.y, w1.z, fmaf(l0.x, w0.z, a0.z + base.z)))), 0.f);
        h.w = fmaxf(fmaf(l0.w, w3.w, fmaf(l0.z, w2.w, fmaf(l0.y, w1.w, fmaf(l0.x, w0.w, a0.w + base.w)))), 0.f);
        acc.x += h.x; acc.y += h.y; acc.z += h.z; acc.w += h.w;
        h.x = fmaxf(fmaf(l1.w, w3.x, fmaf(l1.z, w2.x, fmaf(l1.y, w1.x, fmaf(l1.x, w0.x, a1.x + base.x)))), 0.f);
        h.y = fmaxf(fmaf(l1.w, w3.y, fmaf(l1.z, w2.y, fmaf(l1.y, w1.y, fmaf(l1.x, w0.y, a1.y + base.y)))), 0.f);
        h.z = fmaxf(fmaf(l1.w, w3.z, fmaf(l1.z, w2.z, fmaf(l1.y, w1.z, fmaf(l1.x, w0.z, a1.z + base.z)))), 0.f);
        h.w = fmaxf(fmaf(l1.w, w3.w, fmaf(l1.z, w2.w, fmaf(l1.y, w1.w, fmaf(l1.x, w0.w, a1.w + base.w)))), 0.f);
        acc.x += h.x; acc.y += h.y; acc.z += h.z; acc.w += h.w;
    }
    if (i < e) {
        int s0 = g_esrc[i];
        float4 l0 = g_el[i];
        float4 a0 = *(const float4*)(g_AB + (size_t)s0 * 256 + lane * 4);
        float4 h;
        h.x = fmaxf(fmaf(l0.w, w3.x, fmaf(l0.z, w2.x, fmaf(l0.y, w1.x, fmaf(l0.x, w0.x, a0.x + base.x)))), 0.f);
        h.y = fmaxf(fmaf(l0.w, w3.y, fmaf(l0.z, w2.y, fmaf(l0.y, w1.y, fmaf(l0.x, w0.y, a0.y + base.y)))), 0.f);
        h.z = fmaxf(fmaf(l0.w, w3.z, fmaf(l0.z, w2.z, fmaf(l0.y, w1.z, fmaf(l0.x, w0.z, a0.z + base.z)))), 0.f);
        h.w = fmaxf(fmaf(l0.w, w3.w, fmaf(l0.z, w2.w, fmaf(l0.y, w1.w, fmaf(l0.x, w0.w, a0.w + base.w)))), 0.f);
        acc.x += h.x; acc.y += h.y; acc.z += h.z; acc.w += h.w;
    }
    *(float4*)(g_Hagg + (size_t)d * 128 + lane * 4) = acc;
}

// ---------------- GEMM1 (tensor core): AB = x @ [W1a|W1b] -------------------------
__global__ __launch_bounds__(256) void mma_gemm1_kernel(const float* __restrict__ a_x) {
    __shared__ __align__(16) u32 sA[2][128][20];
    const int tid = threadIdx.x;
    const int lane = tid & 31;
    const int warp = tid >> 5;
    const int wm = warp >> 1, wn = warp & 1;
    const int q = lane & 3, lr = lane >> 2;
    const int row0 = blockIdx.x * 128;
    const int cb = blockIdx.y;
    const u32* __restrict__ Bhi = g_Bp1hi + cb * 4096;
    const u32* __restrict__ Blo = g_Bp1lo + cb * 4096;

    float acc[2][8][4];
#pragma unroll
    for (int i = 0; i < 2; i++)
#pragma unroll
        for (int j = 0; j < 8; j++)
#pragma unroll
            for (int p = 0; p < 4; p++) acc[i][j][p] = 0.f;

    for (int ch = 0; ch < 2; ch++) {
        const int kc0 = ch * 32;
        __syncthreads();
#pragma unroll
        for (int it = 0; it < 4; it++) {
            int idx = tid + it * 256;
            int m = idx >> 3, fx = idx & 7;
            int gm = row0 + m;
            if (gm >= N_NODES) gm = N_NODES - 1;
            float4 v = *(const float4*)(a_x + (size_t)gm * 64 + kc0 + fx * 4);
            u32 h0 = pack_hi(v.x, v.y), h1 = pack_hi(v.z, v.w);
            u32 l0 = pack_lo(v.x, v.y), l1 = pack_lo(v.z, v.w);
            *(u64t*)&sA[0][m][fx * 2] = ((u64t)h1 << 32) | h0;
            *(u64t*)&sA[1][m][fx * 2] = ((u64t)l1 << 32) | l0;
        }
        __syncthreads();
#pragma unroll
        for (int s = 0; s < 2; s++) {
            const int sg = ch * 2 + s;
            u32 ah[2][4], al[2][4];
#pragma unroll
            for (int i = 0; i < 2; i++) {
                int rr = wm * 32 + i * 16 + lr;
                ah[i][0] = sA[0][rr][8 * s + q];
                ah[i][1] = sA[0][rr + 8][8 * s + q];
                ah[i][2] = sA[0][rr][8 * s + q + 4];
                ah[i][3] = sA[0][rr + 8][8 * s + q + 4];
                al[i][0] = sA[1][rr][8 * s + q];
                al[i][1] = sA[1][rr + 8][8 * s + q];
                al[i][2] = sA[1][rr][8 * s + q + 4];
                al[i][3] = sA[1][rr + 8][8 * s + q + 4];
            }
#pragma unroll
            for (int j = 0; j < 8; j++) {
                int c = wn * 64 + j * 8 + lr;
                int bidx = ((sg * 128 + c) * 4 + q) * 2;
                u64t bh = *(const u64t*)(Bhi + bidx);
                u64t bl = *(const u64t*)(Blo + bidx);
                u32 bh0 = (u32)bh, bh1 = (u32)(bh >> 32);
                u32 bl0 = (u32)bl, bl1 = (u32)(bl >> 32);
#pragma unroll
                for (int i = 0; i < 2; i++) {
                    mma16816(acc[i][j], ah[i], bh0, bh1);
                    mma16816(acc[i][j], al[i], bh0, bh1);
                    mma16816(acc[i][j], ah[i], bl0, bl1);
                }
            }
        }
    }
    const int rbase = row0 + wm * 32 + lr;
#pragma unroll
    for (int i = 0; i < 2; i++) {
        int r0 = rbase + i * 16, r1 = r0 + 8;
#pragma unroll
        for (int j = 0; j < 8; j++) {
            int n = wn * 64 + j * 8 + 2 * q;
            if (r0 < N_NODES)
                *(float2*)(g_AB + (size_t)r0 * 256 + cb * 128 + n) = make_float2(acc[i][j][0], acc[i][j][1]);
            if (r1 < N_NODES)
                *(float2*)(g_AB + (size_t)r1 * 256 + cb * 128 + n) = make_float2(acc[i][j][2], acc[i][j][3]);
        }
    }
}

// ---------------- fused update: out = relu([x|Hagg]@Wcat + deg*dvec + bu1)@U2 + bu2
#define SA_(h, m, w) sraw[((h)*128 + (m)) * 20 + (w)]
#define SG_(h, m, w) sraw[((h)*128 + (m)) * 68 + (w)]

__global__ __launch_bounds__(256) void fused_upd_kernel(const float* __restrict__ a_x,
                                                        const float* __restrict__ bu1,
                                                        const float* __restrict__ bu2,
                                                        float* __restrict__ outp) {
    extern __shared__ __align__(16) u32 sraw[];   // 2*128*68 u32 = 69632 B
    const int tid = threadIdx.x;
    const int lane = tid & 31;
    const int warp = tid >> 5;
    const int wm = warp >> 1, wn = warp & 1;
    const int q = lane & 3, lr = lane >> 2;
    const int row0 = blockIdx.x * 128;

    float acc[2][8][4];
#pragma unroll
    for (int i = 0; i < 2; i++)
#pragma unroll
        for (int j = 0; j < 8; j++)
#pragma unroll
            for (int p = 0; p < 4; p++) acc[i][j][p] = 0.f;

    // ---- stage 1: [x|Hagg] @ Wcat (K=192) ----
    for (int ch = 0; ch < 6; ch++) {
        const int kc0 = ch * 32;
        const float* srcp;
        int ld, koff;
        if (kc0 < 64) { srcp = a_x;                  ld = 64;  koff = kc0; }
        else          { srcp = (const float*)g_Hagg; ld = 128; koff = kc0 - 64; }
        __syncthreads();
#pragma unroll
        for (int it = 0; it < 4; it++) {
            int idx = tid + it * 256;
            int m = idx >> 3, fx = idx & 7;
            int gm = row0 + m;
            if (gm >= N_NODES) gm = N_NODES - 1;
            float4 v = *(const float4*)(srcp + (size_t)gm * ld + koff + fx * 4);
            u32 h0 = pack_hi(v.x, v.y), h1 = pack_hi(v.z, v.w);
            u32 l0 = pack_lo(v.x, v.y), l1 = pack_lo(v.z, v.w);
            *(u64t*)&SA_(0, m, fx * 2) = ((u64t)h1 << 32) | h0;
            *(u64t*)&SA_(1, m, fx * 2) = ((u64t)l1 << 32) | l0;
        }
        __syncthreads();
#pragma unroll
        for (int s = 0; s < 2; s++) {
            const int sg = ch * 2 + s;
            u32 ah[2][4], al[2][4];
#pragma unroll
            for (int i = 0; i < 2; i++) {
                int rr = wm * 32 + i * 16 + lr;
                ah[i][0] = SA_(0, rr, 8 * s + q);
                ah[i][1] = SA_(0, rr + 8, 8 * s + q);
                ah[i][2] = SA_(0, rr, 8 * s + q + 4);
                ah[i][3] = SA_(0, rr + 8, 8 * s + q + 4);
                al[i][0] = SA_(1, rr, 8 * s + q);
                al[i][1] = SA_(1, rr + 8, 8 * s + q);
                al[i][2] = SA_(1, rr, 8 * s + q + 4);
                al[i][3] = SA_(1, rr + 8, 8 * s + q + 4);
            }
#pragma unroll
            for (int j = 0; j < 8; j++) {
                int c = wn * 64 + j * 8 + lr;
                int bidx = ((sg * 128 + c) * 4 + q) * 2;
                u64t bh = *(const u64t*)(g_Bp2hi + bidx);
                u64t bl = *(const u64t*)(g_Bp2lo + bidx);
                u32 bh0 = (u32)bh, bh1 = (u32)(bh >> 32);
                u32 bl0 = (u32)bl, bl1 = (u32)(bl >> 32);
#pragma unroll
                for (int i = 0; i < 2; i++) {
                    mma16816(acc[i][j], ah[i], bh0, bh1);
                    mma16816(acc[i][j], al[i], bh0, bh1);
                    mma16816(acc[i][j], ah[i], bl0, bl1);
                }
            }
        }
    }

    // ---- epilogue 1: relu(acc + deg*dvec + bu1) -> sG (bf16 hi/lo) ----
    __syncthreads();   // all SA reads done before aliasing as SG
#pragma unroll
    for (int i = 0; i < 2; i++) {
        int rl0 = wm * 32 + i * 16 + lr;
        int rl1 = rl0 + 8;
        int gr0 = row0 + rl0;
        int gr1 = row0 + rl1;
        if (gr0 >= N_NODES) gr0 = N_NODES - 1;
        if (gr1 >= N_NODES) gr1 = N_NODES - 1;
        float dg0 = (float)(g_rp[gr0 + 1] - g_rp[gr0]);
        float dg1 = (float)(g_rp[gr1 + 1] - g_rp[gr1]);
#pragma unroll
        for (int j = 0; j < 8; j++) {
            int n = wn * 64 + j * 8 + 2 * q;
            float dv0 = g_dvec[n], dv1 = g_dvec[n + 1];
            float u0 = bu1[n], u1 = bu1[n + 1];
            float o0 = fmaxf(acc[i][j][0] + fmaf(dg0, dv0, u0), 0.f);
            float o1 = fmaxf(acc[i][j][1] + fmaf(dg0, dv1, u1), 0.f);
            float o2 = fmaxf(acc[i][j][2] + fmaf(dg1, dv0, u0), 0.f);
            float o3 = fmaxf(acc[i][j][3] + fmaf(dg1, dv1, u1), 0.f);
            int w = wn * 32 + j * 4 + q;
            SG_(0, rl0, w) = pack_hi(o0, o1);
            SG_(1, rl0, w) = pack_lo(o0, o1);
            SG_(0, rl1, w) = pack_hi(o2, o3);
            SG_(1, rl1, w) = pack_lo(o2, o3);
        }
    }
    __syncthreads();

    // ---- stage 2: G @ U2 (K=128, N=64) ----
    float acc2[2][4][4];
#pragma unroll
    for (int i = 0; i < 2; i++)
#pragma unroll
        for (int j = 0; j < 4; j++)
#pragma unroll
            for (int p = 0; p < 4; p++) acc2[i][j][p] = 0.f;

#pragma unroll
    for (int s2 = 0; s2 < 8; s2++) {
        u32 ah[2][4], al[2][4];
#pragma unroll
        for (int i = 0; i < 2; i++) {
            int rr = wm * 32 + i * 16 + lr;
            ah[i][0] = SG_(0, rr, 8 * s2 + q);
            ah[i][1] = SG_(0, rr + 8, 8 * s2 + q);
            ah[i][2] = SG_(0, rr, 8 * s2 + q + 4);
            ah[i][3] = SG_(0, rr + 8, 8 * s2 + q + 4);
            al[i][0] = SG_(1, rr, 8 * s2 + q);
            al[i][1] = SG_(1, rr + 8, 8 * s2 + q);
            al[i][2] = SG_(1, rr, 8 * s2 + q + 4);
            al[i][3] = SG_(1, rr + 8, 8 * s2 + q + 4);
        }
#pragma unroll
        for (int j = 0; j < 4; j++) {
            int c = wn * 32 + j * 8 + lr;
            int bidx = ((s2 * 64 + c) * 4 + q) * 2;
            u64t bh = *(const u64t*)(g_Bp3hi + bidx);
            u64t bl = *(const u64t*)(g_Bp3lo + bidx);
            u32 bh0 = (u32)bh, bh1 = (u32)(bh >> 32);
            u32 bl0 = (u32)bl, bl1 = (u32)(bl >> 32);
#pragma unroll
            for (int i = 0; i < 2; i++) {
                mma16816(acc2[i][j], ah[i], bh0, bh1);
                mma16816(acc2[i][j], al[i], bh0, bh1);
                mma16816(acc2[i][j], ah[i], bl0, bl1);
            }
        }
    }

    // ---- epilogue 2: + bu2 -> out ----
    const int rbase = row0 + wm * 32 + lr;
#pragma unroll
    for (int i = 0; i < 2; i++) {
        int r0 = rbase + i * 16, r1 = r0 + 8;
#pragma unroll
        for (int j = 0; j < 4; j++) {
            int n = wn * 32 + j * 8 + 2 * q;
            float u0 = bu2[n], u1 = bu2[n + 1];
            if (r0 < N_NODES)
                *(float2*)(outp + (size_t)r0 * 64 + n) =
                    make_float2(acc2[i][j][0] + u0, acc2[i][j][1] + u1);
            if (r1 < N_NODES)
                *(float2*)(outp + (size_t)r1 * 64 + n) =
                    make_float2(acc2[i][j][2] + u0, acc2[i][j][3] + u1);
        }
    }
}

// ---------------- launch ----------------------------------------------------------
extern "C" void kernel_launch(void* const* d_in, const int* in_sizes, int n_in,
                              void* d_out, int out_size) {
    const float* x   = (const float*)d_in[0];
    const int*   ei  = (const int*)d_in[1];
    const float* ef  = (const float*)d_in[2];
    const float* W1  = (const float*)d_in[3];
    const float* b1  = (const float*)d_in[4];
    const float* W2  = (const float*)d_in[5];
    const float* b2  = (const float*)d_in[6];
    const float* U1  = (const float*)d_in[7];
    const float* bu1 = (const float*)d_in[8];
    const float* U2  = (const float*)d_in[9];
    const float* bu2 = (const float*)d_in[10];
    float* out = (float*)d_out;

    cudaFuncSetAttribute(fused_upd_kernel, cudaFuncAttributeMaxDynamicSharedMemorySize, 69632);

    prep_kernel<<<193, 128>>>(W2, b2, U1);
    pack_all_kernel<<<96, 256>>>(W1, U2);
    mma_gemm1_kernel<<<dim3(782, 2), 256>>>(x);
    zero_cnt_kernel<<<98, 1024>>>();
    hist_kernel<<<782, 1024>>>(ei);
    scan_blk_kernel<<<SCAN_BLOCKS, 256>>>();
    scan_top_kernel<<<1, 512>>>();
    scan_fin_kernel<<<SCAN_BLOCKS, 256>>>();
    scatter_kernel<<<782, 1024>>>(ei, ef);
    agg_kernel<<<12500, 256>>>(W1, b1);
    fused_upd_kernel<<<782, 256, 69632>>>(x, bu1, bu2, out);
}

// round 7
// speedup vs baseline: 1.3633x; 1.0328x over previous
#include <cuda_runtime.h>
#include <cuda_bf16.h>
#include <math.h>
#include <stdint.h>

#define N_NODES 100000
#define N_EDGES 800000
#define SCAN_BLOCKS 391   // ceil(100000/256)

typedef unsigned int u32;
typedef unsigned long long u64t;

// ---------------- scratch ----------------------------------------------------------
__device__ float g_A[(size_t)N_NODES * 128];     // x@W1a  (edge-gather set, L2-resident)
__device__ float g_B[(size_t)N_NODES * 128];     // x@W1b  (streamed once per node)
__device__ float g_Hagg[(size_t)N_NODES * 128];  // sum over in-edges of relu(h)
__device__ float g_Wcat[192 * 128];              // [U1a ; V=W2@U1b]
__device__ float g_dvec[128];                    // b2 @ U1b

// CSR by destination
__device__ int    g_cnt[N_NODES];
__device__ int    g_rp[N_NODES + 1];
__device__ int    g_pos[N_NODES];
__device__ int    g_blksum[SCAN_BLOCKS];
__device__ int    g_blkoff[SCAN_BLOCKS];
__device__ int    g_esrc[N_EDGES];
__device__ float4 g_el[N_EDGES];                 // log1p(edge features), CSR order

// pre-packed mma B fragments (hi/lo bf16 pairs), layout: ((s*N + c)*4 + q)*2 + h
__device__ u32 g_Bp1hi[2 * 4096];
__device__ u32 g_Bp1lo[2 * 4096];
__device__ u32 g_Bp2hi[12288];
__device__ u32 g_Bp2lo[12288];
__device__ u32 g_Bp3hi[4096];
__device__ u32 g_Bp3lo[4096];

// ---------------- helpers ----------------------------------------------------------
__device__ __forceinline__ u32 bf16bits(float x) {
    return (u32)__bfloat16_as_ushort(__float2bfloat16_rn(x));
}
__device__ __forceinline__ float bf16val(float x) {
    return __bfloat162float(__float2bfloat16_rn(x));
}
__device__ __forceinline__ u32 pack_hi(float x, float y) {
    return bf16bits(x) | (bf16bits(y) << 16);
}
__device__ __forceinline__ u32 pack_lo(float x, float y) {
    return bf16bits(x - bf16val(x)) | (bf16bits(y - bf16val(y)) << 16);
}

__device__ __forceinline__ void mma16816(float c[4], const u32 a[4], u32 b0, u32 b1) {
    asm volatile(
        "mma.sync.aligned.m16n8k16.row.col.f32.bf16.bf16.f32 "
        "{%0,%1,%2,%3}, {%4,%5,%6,%7}, {%8,%9}, {%0,%1,%2,%3};"
        : "+f"(c[0]), "+f"(c[1]), "+f"(c[2]), "+f"(c[3])
        : "r"(a[0]), "r"(a[1]), "r"(a[2]), "r"(a[3]), "r"(b0), "r"(b1));
}

// edge message contribution: relu(a + base + sum l_i * w_i)
__device__ __forceinline__ void msg_acc(float4& acc, const float4& a, const float4& base,
                                        const float4& l, const float4& w0, const float4& w1,
                                        const float4& w2, const float4& w3) {
    acc.x += fmaxf(fmaf(l.w, w3.x, fmaf(l.z, w2.x, fmaf(l.y, w1.x, fmaf(l.x, w0.x, a.x + base.x)))), 0.f);
    acc.y += fmaxf(fmaf(l.w, w3.y, fmaf(l.z, w2.y, fmaf(l.y, w1.y, fmaf(l.x, w0.y, a.y + base.y)))), 0.f);
    acc.z += fmaxf(fmaf(l.w, w3.z, fmaf(l.z, w2.z, fmaf(l.y, w1.z, fmaf(l.x, w0.z, a.z + base.z)))), 0.f);
    acc.w += fmaxf(fmaf(l.w, w3.w, fmaf(l.z, w2.w, fmaf(l.y, w1.w, fmaf(l.x, w0.w, a.w + base.w)))), 0.f);
}

// ---------------- prep: build Wcat and dvec ---------------------------------------
__global__ void prep_kernel(const float* __restrict__ W2, const float* __restrict__ b2,
                            const float* __restrict__ U1) {
    int b = blockIdx.x, j = threadIdx.x;
    if (b < 64) {
        g_Wcat[b * 128 + j] = U1[b * 128 + j];
    } else if (b < 192) {
        int i = b - 64;
        float s = 0.f;
#pragma unroll
        for (int k = 0; k < 64; k++)
            s = fmaf(W2[i * 64 + k], U1[(64 + k) * 128 + j], s);
        g_Wcat[b * 128 + j] = s;
    } else {
        float s = 0.f;
#pragma unroll
        for (int k = 0; k < 64; k++)
            s = fmaf(b2[k], U1[(64 + k) * 128 + j], s);
        g_dvec[j] = s;
    }
}

// ---------------- pack all B matrices (one launch) --------------------------------
__global__ void pack_all_kernel(const float* __restrict__ W1, const float* __restrict__ U2) {
    int idx = blockIdx.x * blockDim.x + threadIdx.x;  // 0 .. 24575
    u32 *dh, *dl;
    const float* src;
    int N;
    if (idx < 4096)        { dh = g_Bp1hi;        dl = g_Bp1lo;        src = W1;            N = 128; }
    else if (idx < 8192)   { dh = g_Bp1hi + 4096; dl = g_Bp1lo + 4096; src = W1 + 64 * 128; N = 128; idx -= 4096; }
    else if (idx < 20480)  { dh = g_Bp2hi;        dl = g_Bp2lo;        src = g_Wcat;        N = 128; idx -= 8192; }
    else                   { dh = g_Bp3hi;        dl = g_Bp3lo;        src = U2;            N = 64;  idx -= 20480; }

    int h = idx & 1;
    int rest = idx >> 1;
    int q = rest & 3;
    int rest2 = rest >> 2;
    int c = rest2 % N;
    int s = rest2 / N;
    int k0 = 16 * s + 2 * q + 8 * h;
    float f0 = src[(size_t)k0 * N + c];
    float f1 = src[(size_t)(k0 + 1) * N + c];
    dh[idx] = pack_hi(f0, f1);
    dl[idx] = pack_lo(f0, f1);
}

// ---------------- CSR build --------------------------------------------------------
__global__ void zero_cnt_kernel() {
    int i = blockIdx.x * blockDim.x + threadIdx.x;
    if (i < N_NODES) g_cnt[i] = 0;
}

__global__ void hist_kernel(const int* __restrict__ ei) {
    int e = blockIdx.x * blockDim.x + threadIdx.x;
    if (e < N_EDGES) atomicAdd(&g_cnt[ei[N_EDGES + e]], 1);
}

__global__ void scan_blk_kernel() {
    __shared__ int sh[256];
    int t = threadIdx.x;
    int i = blockIdx.x * 256 + t;
    int c = (i < N_NODES) ? g_cnt[i] : 0;
    sh[t] = c;
    __syncthreads();
    for (int off = 128; off > 0; off >>= 1) {
        if (t < off) sh[t] += sh[t + off];
        __syncthreads();
    }
    if (t == 0) g_blksum[blockIdx.x] = sh[0];
}

__global__ void scan_top_kernel() {
    __shared__ int sh[512];
    int t = threadIdx.x;
    int v = (t < SCAN_BLOCKS) ? g_blksum[t] : 0;
    sh[t] = v;
    __syncthreads();
    for (int off = 1; off < 512; off <<= 1) {
        int add = (t >= off) ? sh[t - off] : 0;
        __syncthreads();
        sh[t] += add;
        __syncthreads();
    }
    if (t < SCAN_BLOCKS) g_blkoff[t] = sh[t] - v;  // exclusive
    if (t == 0) g_rp[N_NODES] = N_EDGES;
}

__global__ void scan_fin_kernel() {
    __shared__ int sh[256];
    int t = threadIdx.x;
    int i = blockIdx.x * 256 + t;
    int c = (i < N_NODES) ? g_cnt[i] : 0;
    sh[t] = c;
    __syncthreads();
    for (int off = 1; off < 256; off <<= 1) {
        int add = (t >= off) ? sh[t - off] : 0;
        __syncthreads();
        sh[t] += add;
        __syncthreads();
    }
    if (i < N_NODES) {
        int excl = g_blkoff[blockIdx.x] + sh[t] - c;
        g_rp[i] = excl;
        g_pos[i] = excl;
    }
}

__global__ void scatter_kernel(const int* __restrict__ ei, const float* __restrict__ ef) {
    int e = blockIdx.x * blockDim.x + threadIdx.x;
    if (e >= N_EDGES) return;
    int s = ei[e];
    int d = ei[N_EDGES + e];
    int p = atomicAdd(&g_pos[d], 1);
    g_esrc[p] = s;
    float4 l;
    l.x = log1pf(ef[(size_t)e * 4 + 0]);
    l.y = log1pf(ef[(size_t)e * 4 + 1]);
    l.z = log1pf(ef[(size_t)e * 4 + 2]);
    l.w = log1pf(ef[(size_t)e * 4 + 3]);
    g_el[p] = l;
}

// ---------------- aggregation: warp per destination node, unroll 4 -----------------
__global__ __launch_bounds__(256) void agg_kernel(const float* __restrict__ W1,
                                                  const float* __restrict__ b1) {
    __shared__ float s_wc[512];
    __shared__ float s_b1[128];
    for (int t = threadIdx.x; t < 512; t += 256) s_wc[t] = W1[128 * 128 + t];
    if (threadIdx.x < 128) s_b1[threadIdx.x] = b1[threadIdx.x];
    __syncthreads();

    int warp = threadIdx.x >> 5;
    int lane = threadIdx.x & 31;
    int d = blockIdx.x * 8 + warp;   // grid = 12500 -> exactly 100000
    int s = g_rp[d];
    int e = g_rp[d + 1];

    float4 w0 = *(const float4*)&s_wc[0 * 128 + lane * 4];
    float4 w1 = *(const float4*)&s_wc[1 * 128 + lane * 4];
    float4 w2 = *(const float4*)&s_wc[2 * 128 + lane * 4];
    float4 w3 = *(const float4*)&s_wc[3 * 128 + lane * 4];
    float4 base = *(const float4*)(g_B + (size_t)d * 128 + lane * 4);
    float4 bb = *(const float4*)&s_b1[lane * 4];
    base.x += bb.x; base.y += bb.y; base.z += bb.z; base.w += bb.w;

    float4 acc = make_float4(0.f, 0.f, 0.f, 0.f);
    int i = s;
    for (; i + 4 <= e; i += 4) {
        int s0 = g_esrc[i], s1 = g_esrc[i + 1], s2 = g_esrc[i + 2], s3 = g_esrc[i + 3];
        float4 a0 = *(const float4*)(g_A + (size_t)s0 * 128 + lane * 4);
        float4 a1 = *(const float4*)(g_A + (size_t)s1 * 128 + lane * 4);
        float4 a2 = *(const float4*)(g_A + (size_t)s2 * 128 + lane * 4);
        float4 a3 = *(const float4*)(g_A + (size_t)s3 * 128 + lane * 4);
        float4 l0 = g_el[i], l1 = g_el[i + 1], l2 = g_el[i + 2], l3 = g_el[i + 3];
        msg_acc(acc, a0, base, l0, w0, w1, w2, w3);
        msg_acc(acc, a1, base, l1, w0, w1, w2, w3);
        msg_acc(acc, a2, base, l2, w0, w1, w2, w3);
        msg_acc(acc, a3, base, l3, w0, w1, w2, w3);
    }
    for (; i < e; i++) {
        int s0 = g_esrc[i];
        float4 a0 = *(const float4*)(g_A + (size_t)s0 * 128 + lane * 4);
        float4 l0 = g_el[i];
        msg_acc(acc, a0, base, l0, w0, w1, w2, w3);
    }
    *(float4*)(g_Hagg + (size_t)d * 128 + lane * 4) = acc;
}

// ---------------- GEMM1 (tensor core): g_A = x@W1a, g_B = x@W1b -------------------
__global__ __launch_bounds__(256) void mma_gemm1_kernel(const float* __restrict__ a_x) {
    __shared__ __align__(16) u32 sA[2][128][20];
    const int tid = threadIdx.x;
    const int lane = tid & 31;
    const int warp = tid >> 5;
    const int wm = warp >> 1, wn = warp & 1;
    const int q = lane & 3, lr = lane >> 2;
    const int row0 = blockIdx.x * 128;
    const int cb = blockIdx.y;
    const u32* __restrict__ Bhi = g_Bp1hi + cb * 4096;
    const u32* __restrict__ Blo = g_Bp1lo + cb * 4096;
    float* __restrict__ dst = cb ? g_B : g_A;

    float acc[2][8][4];
#pragma unroll
    for (int i = 0; i < 2; i++)
#pragma unroll
        for (int j = 0; j < 8; j++)
#pragma unroll
            for (int p = 0; p < 4; p++) acc[i][j][p] = 0.f;

    for (int ch = 0; ch < 2; ch++) {
        const int kc0 = ch * 32;
        __syncthreads();
#pragma unroll
        for (int it = 0; it < 4; it++) {
            int idx = tid + it * 256;
            int m = idx >> 3, fx = idx & 7;
            int gm = row0 + m;
            if (gm >= N_NODES) gm = N_NODES - 1;
            float4 v = *(const float4*)(a_x + (size_t)gm * 64 + kc0 + fx * 4);
            u32 h0 = pack_hi(v.x, v.y), h1 = pack_hi(v.z, v.w);
            u32 l0 = pack_lo(v.x, v.y), l1 = pack_lo(v.z, v.w);
            *(u64t*)&sA[0][m][fx * 2] = ((u64t)h1 << 32) | h0;
            *(u64t*)&sA[1][m][fx * 2] = ((u64t)l1 << 32) | l0;
        }
        __syncthreads();
#pragma unroll
        for (int s = 0; s < 2; s++) {
            const int sg = ch * 2 + s;
            u32 ah[2][4], al[2][4];
#pragma unroll
            for (int i = 0; i < 2; i++) {
                int rr = wm * 32 + i * 16 + lr;
                ah[i][0] = sA[0][rr][8 * s + q];
                ah[i][1] = sA[0][rr + 8][8 * s + q];
                ah[i][2] = sA[0][rr][8 * s + q + 4];
                ah[i][3] = sA[0][rr + 8][8 * s + q + 4];
                al[i][0] = sA[1][rr][8 * s + q];
                al[i][1] = sA[1][rr + 8][8 * s + q];
                al[i][2] = sA[1][rr][8 * s + q + 4];
                al[i][3] = sA[1][rr + 8][8 * s + q + 4];
            }
#pragma unroll
            for (int j = 0; j < 8; j++) {
                int c = wn * 64 + j * 8 + lr;
                int bidx = ((sg * 128 + c) * 4 + q) * 2;
                u64t bh = *(const u64t*)(Bhi + bidx);
                u64t bl = *(const u64t*)(Blo + bidx);
                u32 bh0 = (u32)bh, bh1 = (u32)(bh >> 32);
                u32 bl0 = (u32)bl, bl1 = (u32)(bl >> 32);
#pragma unroll
                for (int i = 0; i < 2; i++) {
                    mma16816(acc[i][j], ah[i], bh0, bh1);
                    mma16816(acc[i][j], al[i], bh0, bh1);
                    mma16816(acc[i][j], ah[i], bl0, bl1);
                }
            }
        }
    }
    const int rbase = row0 + wm * 32 + lr;
#pragma unroll
    for (int i = 0; i < 2; i++) {
        int r0 = rbase + i * 16, r1 = r0 + 8;
#pragma unroll
        for (int j = 0; j < 8; j++) {
            int n = wn * 64 + j * 8 + 2 * q;
            if (r0 < N_NODES)
                *(float2*)(dst + (size_t)r0 * 128 + n) = make_float2(acc[i][j][0], acc[i][j][1]);
            if (r1 < N_NODES)
                *(float2*)(dst + (size_t)r1 * 128 + n) = make_float2(acc[i][j][2], acc[i][j][3]);
        }
    }
}

// ---------------- fused update: out = relu([x|Hagg]@Wcat + deg*dvec + bu1)@U2 + bu2
#define SA_(h, m, w) sraw[((h)*128 + (m)) * 20 + (w)]
#define SG_(h, m, w) sraw[((h)*128 + (m)) * 68 + (w)]

__global__ __launch_bounds__(256) void fused_upd_kernel(const float* __restrict__ a_x,
                                                        const float* __restrict__ bu1,
                                                        const float* __restrict__ bu2,
                                                        float* __restrict__ outp) {
    extern __shared__ __align__(16) u32 sraw[];   // 2*128*68 u32 = 69632 B
    const int tid = threadIdx.x;
    const int lane = tid & 31;
    const int warp = tid >> 5;
    const int wm = warp >> 1, wn = warp & 1;
    const int q = lane & 3, lr = lane >> 2;
    const int row0 = blockIdx.x * 128;

    float acc[2][8][4];
#pragma unroll
    for (int i = 0; i < 2; i++)
#pragma unroll
        for (int j = 0; j < 8; j++)
#pragma unroll
            for (int p = 0; p < 4; p++) acc[i][j][p] = 0.f;

    // ---- stage 1: [x|Hagg] @ Wcat (K=192) ----
    for (int ch = 0; ch < 6; ch++) {
        const int kc0 = ch * 32;
        const float* srcp;
        int ld, koff;
        if (kc0 < 64) { srcp = a_x;                  ld = 64;  koff = kc0; }
        else          { srcp = (const float*)g_Hagg; ld = 128; koff = kc0 - 64; }
        __syncthreads();
#pragma unroll
        for (int it = 0; it < 4; it++) {
            int idx = tid + it * 256;
            int m = idx >> 3, fx = idx & 7;
            int gm = row0 + m;
            if (gm >= N_NODES) gm = N_NODES - 1;
            float4 v = *(const float4*)(srcp + (size_t)gm * ld + koff + fx * 4);
            u32 h0 = pack_hi(v.x, v.y), h1 = pack_hi(v.z, v.w);
            u32 l0 = pack_lo(v.x, v.y), l1 = pack_lo(v.z, v.w);
            *(u64t*)&SA_(0, m, fx * 2) = ((u64t)h1 << 32) | h0;
            *(u64t*)&SA_(1, m, fx * 2) = ((u64t)l1 << 32) | l0;
        }
        __syncthreads();
#pragma unroll
        for (int s = 0; s < 2; s++) {
            const int sg = ch * 2 + s;
            u32 ah[2][4], al[2][4];
#pragma unroll
            for (int i = 0; i < 2; i++) {
                int rr = wm * 32 + i * 16 + lr;
                ah[i][0] = SA_(0, rr, 8 * s + q);
                ah[i][1] = SA_(0, rr + 8, 8 * s + q);
                ah[i][2] = SA_(0, rr, 8 * s + q + 4);
                ah[i][3] = SA_(0, rr + 8, 8 * s + q + 4);
                al[i][0] = SA_(1, rr, 8 * s + q);
                al[i][1] = SA_(1, rr + 8, 8 * s + q);
                al[i][2] = SA_(1, rr, 8 * s + q + 4);
                al[i][3] = SA_(1, rr + 8, 8 * s + q + 4);
            }
#pragma unroll
            for (int j = 0; j < 8; j++) {
                int c = wn * 64 + j * 8 + lr;
                int bidx = ((sg * 128 + c) * 4 + q) * 2;
                u64t bh = *(const u64t*)(g_Bp2hi + bidx);
                u64t bl = *(const u64t*)(g_Bp2lo + bidx);
                u32 bh0 = (u32)bh, bh1 = (u32)(bh >> 32);
                u32 bl0 = (u32)bl, bl1 = (u32)(bl >> 32);
#pragma unroll
                for (int i = 0; i < 2; i++) {
                    mma16816(acc[i][j], ah[i], bh0, bh1);
                    mma16816(acc[i][j], al[i], bh0, bh1);
                    mma16816(acc[i][j], ah[i], bl0, bl1);
                }
            }
        }
    }

    // ---- epilogue 1: relu(acc + deg*dvec + bu1) -> sG (bf16 hi/lo) ----
    __syncthreads();   // all SA reads done before aliasing as SG
#pragma unroll
    for (int i = 0; i < 2; i++) {
        int rl0 = wm * 32 + i * 16 + lr;
        int rl1 = rl0 + 8;
        int gr0 = row0 + rl0;
        int gr1 = row0 + rl1;
        if (gr0 >= N_NODES) gr0 = N_NODES - 1;
        if (gr1 >= N_NODES) gr1 = N_NODES - 1;
        float dg0 = (float)(g_rp[gr0 + 1] - g_rp[gr0]);
        float dg1 = (float)(g_rp[gr1 + 1] - g_rp[gr1]);
#pragma unroll
        for (int j = 0; j < 8; j++) {
            int n = wn * 64 + j * 8 + 2 * q;
            float dv0 = g_dvec[n], dv1 = g_dvec[n + 1];
            float u0 = bu1[n], u1 = bu1[n + 1];
            float o0 = fmaxf(acc[i][j][0] + fmaf(dg0, dv0, u0), 0.f);
            float o1 = fmaxf(acc[i][j][1] + fmaf(dg0, dv1, u1), 0.f);
            float o2 = fmaxf(acc[i][j][2] + fmaf(dg1, dv0, u0), 0.f);
            float o3 = fmaxf(acc[i][j][3] + fmaf(dg1, dv1, u1), 0.f);
            int w = wn * 32 + j * 4 + q;
            SG_(0, rl0, w) = pack_hi(o0, o1);
            SG_(1, rl0, w) = pack_lo(o0, o1);
            SG_(0, rl1, w) = pack_hi(o2, o3);
            SG_(1, rl1, w) = pack_lo(o2, o3);
        }
    }
    __syncthreads();

    // ---- stage 2: G @ U2 (K=128, N=64) ----
    float acc2[2][4][4];
#pragma unroll
    for (int i = 0; i < 2; i++)
#pragma unroll
        for (int j = 0; j < 4; j++)
#pragma unroll
            for (int p = 0; p < 4; p++) acc2[i][j][p] = 0.f;

#pragma unroll
    for (int s2 = 0; s2 < 8; s2++) {
        u32 ah[2][4], al[2][4];
#pragma unroll
        for (int i = 0; i < 2; i++) {
            int rr = wm * 32 + i * 16 + lr;
            ah[i][0] = SG_(0, rr, 8 * s2 + q);
            ah[i][1] = SG_(0, rr + 8, 8 * s2 + q);
            ah[i][2] = SG_(0, rr, 8 * s2 + q + 4);
            ah[i][3] = SG_(0, rr + 8, 8 * s2 + q + 4);
            al[i][0] = SG_(1, rr, 8 * s2 + q);
            al[i][1] = SG_(1, rr + 8, 8 * s2 + q);
            al[i][2] = SG_(1, rr, 8 * s2 + q + 4);
            al[i][3] = SG_(1, rr + 8, 8 * s2 + q + 4);
        }
#pragma unroll
        for (int j = 0; j < 4; j++) {
            int c = wn * 32 + j * 8 + lr;
            int bidx = ((s2 * 64 + c) * 4 + q) * 2;
            u64t bh = *(const u64t*)(g_Bp3hi + bidx);
            u64t bl = *(const u64t*)(g_Bp3lo + bidx);
            u32 bh0 = (u32)bh, bh1 = (u32)(bh >> 32);
            u32 bl0 = (u32)bl, bl1 = (u32)(bl >> 32);
#pragma unroll
            for (int i = 0; i < 2; i++) {
                mma16816(acc2[i][j], ah[i], bh0, bh1);
                mma16816(acc2[i][j], al[i], bh0, bh1);
                mma16816(acc2[i][j], ah[i], bl0, bl1);
            }
        }
    }

    // ---- epilogue 2: + bu2 -> out ----
    const int rbase = row0 + wm * 32 + lr;
#pragma unroll
    for (int i = 0; i < 2; i++) {
        int r0 = rbase + i * 16, r1 = r0 + 8;
#pragma unroll
        for (int j = 0; j < 4; j++) {
            int n = wn * 32 + j * 8 + 2 * q;
            float u0 = bu2[n], u1 = bu2[n + 1];
            if (r0 < N_NODES)
                *(float2*)(outp + (size_t)r0 * 64 + n) =
                    make_float2(acc2[i][j][0] + u0, acc2[i][j][1] + u1);
            if (r1 < N_NODES)
                *(float2*)(outp + (size_t)r1 * 64 + n) =
                    make_float2(acc2[i][j][2] + u0, acc2[i][j][3] + u1);
        }
    }
}

// ---------------- launch ----------------------------------------------------------
extern "C" void kernel_launch(void* const* d_in, const int* in_sizes, int n_in,
                              void* d_out, int out_size) {
    const float* x   = (const float*)d_in[0];
    const int*   ei  = (const int*)d_in[1];
    const float* ef  = (const float*)d_in[2];
    const float* W1  = (const float*)d_in[3];
    const float* b1  = (const float*)d_in[4];
    const float* W2  = (const float*)d_in[5];
    const float* b2  = (const float*)d_in[6];
    const float* U1  = (const float*)d_in[7];
    const float* bu1 = (const float*)d_in[8];
    const float* U2  = (const float*)d_in[9];
    const float* bu2 = (const float*)d_in[10];
    float* out = (float*)d_out;

    cudaFuncSetAttribute(fused_upd_kernel, cudaFuncAttributeMaxDynamicSharedMemorySize, 69632);

    prep_kernel<<<193, 128>>>(W2, b2, U1);
    pack_all_kernel<<<96, 256>>>(W1, U2);
    mma_gemm1_kernel<<<dim3(782, 2), 256>>>(x);
    zero_cnt_kernel<<<98, 1024>>>();
    hist_kernel<<<782, 1024>>>(ei);
    scan_blk_kernel<<<SCAN_BLOCKS, 256>>>();
    scan_top_kernel<<<1, 512>>>();
    scan_fin_kernel<<<SCAN_BLOCKS, 256>>>();
    scatter_kernel<<<782, 1024>>>(ei, ef);
    agg_kernel<<<12500, 256>>>(W1, b1);
    fused_upd_kernel<<<782, 256, 69632>>>(x, bu1, bu2, out);
}